// round 15
// baseline (speedup 1.0000x reference)
#include <cuda_runtime.h>
#include <cuda_bf16.h>
#include <cuda_fp16.h>
#include <math.h>
#include <stdint.h>

// Problem constants
#define R_NODES 10
#define HID 128
#define NE 36
#define BT 12800
#define NODE_F 1280
#define NTOT (BT * NODE_F)
#define LN_EPS 1e-5f
#define NI 3
#define VROWS 30
#define GRID_GAT ((BT + NI - 1) / NI)   // 4267

__device__ float g_nf0[NTOT];
__device__ float g_nf1[NTOT];
// W pre-arranged in mma.sync B-fragment layout:
// [layer][head]{ hi: [wslot(8)][kc(8)][lane(32)] 16B chunks = 32KB, lo: +32KB }
__device__ __align__(16) uint8_t g_Wt[3 * 4 * 65536];

__constant__ int c_start[R_NODES + 1] = {0, 5, 8, 12, 15, 17, 22, 27, 31, 33, 36};
__constant__ int c_src[NE] = {
    9, 5, 6, 1, 0,   0, 2, 1,   5, 1, 3, 2,   2, 4, 3,   3, 4,
    6, 2, 0, 7, 5,   5, 9, 0, 7, 6,   6, 5, 8, 7,   7, 8,   6, 0, 9
};

__device__ __forceinline__ float gelu_exact(float v) {
    return 0.5f * v * (1.0f + erff(v * 0.70710678118654752440f));
}
__device__ __forceinline__ uint32_t smem_u32(const void* p) {
    uint32_t a;
    asm("{ .reg .u64 t; cvta.to.shared.u64 t, %1; cvt.u32.u64 %0, t; }" : "=r"(a) : "l"(p));
    return a;
}
__device__ __forceinline__ void ldsm_x4(uint32_t* r, uint32_t addr) {
    asm volatile("ldmatrix.sync.aligned.m8n8.x4.shared.b16 {%0,%1,%2,%3}, [%4];"
                 : "=r"(r[0]), "=r"(r[1]), "=r"(r[2]), "=r"(r[3]) : "r"(addr));
}
__device__ __forceinline__ void mma_bf16(float* d, const uint32_t* a, uint32_t b0, uint32_t b1) {
    asm volatile("mma.sync.aligned.m16n8k16.row.col.f32.bf16.bf16.f32 "
                 "{%0,%1,%2,%3}, {%4,%5,%6,%7}, {%8,%9}, {%0,%1,%2,%3};"
                 : "+f"(d[0]), "+f"(d[1]), "+f"(d[2]), "+f"(d[3])
                 : "r"(a[0]), "r"(a[1]), "r"(a[2]), "r"(a[3]), "r"(b0), "r"(b1));
}
__device__ __forceinline__ void split_bf16x2(float v0, float v1, uint32_t& hi, uint32_t& lo) {
    __nv_bfloat16 h0 = __float2bfloat16(v0);
    __nv_bfloat16 h1 = __float2bfloat16(v1);
    __nv_bfloat16 l0 = __float2bfloat16(v0 - __bfloat162float(h0));
    __nv_bfloat16 l1 = __float2bfloat16(v1 - __bfloat162float(h1));
    hi = (uint32_t)__bfloat16_as_ushort(h0) | ((uint32_t)__bfloat16_as_ushort(h1) << 16);
    lo = (uint32_t)__bfloat16_as_ushort(l0) | ((uint32_t)__bfloat16_as_ushort(l1) << 16);
}

// ---------------------------------------------------------------------------
// W prep (unchanged)
// ---------------------------------------------------------------------------
__global__ void wt_kernel(const float* __restrict__ Wg) {
    int l = blockIdx.x >> 2, h = blockIdx.x & 3;
    uint8_t* base = g_Wt + (size_t)(l * 4 + h) * 65536;
    const float* W = Wg + l * 65536 + h * 128;   // W[k*512 + n]
    for (int c = threadIdx.x; c < 2048; c += 256) {
        int ws = c >> 8, kc = (c >> 5) & 7, lane = c & 31;
        int n0 = ws * 16 + (lane >> 2);
        int k0 = kc * 16 + 2 * (lane & 3);
        uint32_t hi[4], lo[4];
#pragma unroll
        for (int j = 0; j < 4; ++j) {
            int n = n0 + (j >> 1) * 8;
            int k = k0 + (j & 1) * 8;
            float w0 = W[k * 512 + n];
            float w1 = W[(k + 1) * 512 + n];
            split_bf16x2(w0, w1, hi[j], lo[j]);
        }
        *(uint4*)(base + c * 16)         = make_uint4(hi[0], hi[1], hi[2], hi[3]);
        *(uint4*)(base + 32768 + c * 16) = make_uint4(lo[0], lo[1], lo[2], lo[3]);
    }
}

// ---------------------------------------------------------------------------
// GAT layer (R12 structure). ENC=true additionally runs the per-region
// encoder (Linear(6->128)+LN+GELU) first, writing nf_in (= region_feats out),
// then reads it back (L1-hot) for the A-fill and the residual.
// smem byte map (58048, 3 CTAs/SM):
//   0      A_hi (8192)      8192   A_lo (8192)
//   16384  xp half2 [4][32][66 u32] = 33792
//   50176  att (4096)
//   54272  alsp (1024)      55296  aldp (1024)
//   56320  alpha (1728)
// ---------------------------------------------------------------------------
#define A_LO_B   8192
#define XP_B     16384
#define XPS_U32  66
#define XPH_U32  (32 * XPS_U32)
#define ATT_B    50176
#define ALSP_B   54272
#define ALDP_B   55296
#define ALPHA_B  56320
#define SM_DYNBYTES 58048

template <bool ENC>
__global__ void __launch_bounds__(256, 3) gat_mma_kernel(
    const float* __restrict__ x, const float* __restrict__ Wenc,
    const float* __restrict__ benc, const float* __restrict__ gamma,
    const float* __restrict__ beta,
    float* __restrict__ nf_in,
    const uint8_t* __restrict__ Wt,
    const float* __restrict__ asrc, const float* __restrict__ adst,
    const float* __restrict__ bg, float* __restrict__ nf_out)
{
    extern __shared__ uint8_t smb[];
    const uint32_t sb = smem_u32(smb);
    __half2* s_xph = (__half2*)(smb + XP_B);
    float* s_att   = (float*)(smb + ATT_B);
    float* s_alsp  = (float*)(smb + ALSP_B);
    float* s_aldp  = (float*)(smb + ALDP_B);
    float* s_alpha = (float*)(smb + ALPHA_B);

    const int tid  = threadIdx.x;
    const int wid  = tid >> 5;
    const int lane = tid & 31;
    const int hh   = wid >> 1;          // head 0..3
    const int ch2  = wid & 1;           // col half within head
    const long blk = blockIdx.x;

    if (ENC) {
        // ---- encoder: 30 (inst,region) pairs x 8 threads each ----
        const int g   = tid >> 3;        // pair 0..31
        const int sub = tid & 7;
        const int il  = g / 10, region = g - il * 10;
        const long ig = blk * NI + il;
        const bool valid = (g < 30) && (ig < BT);
        const int k0 = sub * 16;
        float h[16];
        if (valid) {
            const float* xr = x + ig * 60 + region * 6;
            float xv[6];
#pragma unroll
            for (int c = 0; c < 6; ++c) xv[c] = xr[c];
#pragma unroll
            for (int j = 0; j < 16; ++j) {
                int k = k0 + j;
                float a = benc[region * HID + k];
#pragma unroll
                for (int c = 0; c < 6; ++c)
                    a = fmaf(xv[c], Wenc[(region * 6 + c) * HID + k], a);
                h[j] = a;
            }
        } else {
#pragma unroll
            for (int j = 0; j < 16; ++j) h[j] = 0.f;
        }
        float s = 0.f, sq = 0.f;
#pragma unroll
        for (int j = 0; j < 16; ++j) { s += h[j]; sq += h[j] * h[j]; }
#pragma unroll
        for (int o = 1; o < 8; o <<= 1) {
            s  += __shfl_xor_sync(0xffffffffu, s, o);
            sq += __shfl_xor_sync(0xffffffffu, sq, o);
        }
        float mean = s * (1.0f / 128.0f);
        float var  = sq * (1.0f / 128.0f) - mean * mean;
        float rstd = rsqrtf(var + LN_EPS);
        if (valid) {
            float o16[16];
#pragma unroll
            for (int j = 0; j < 16; ++j) {
                int k = k0 + j;
                float v = (h[j] - mean) * rstd * gamma[region * HID + k] + beta[region * HID + k];
                o16[j] = gelu_exact(v);
            }
            float* dst = nf_in + ig * NODE_F + region * HID + k0;
#pragma unroll
            for (int j = 0; j < 4; ++j)
                *(float4*)(dst + j * 4) = make_float4(o16[j*4], o16[j*4+1], o16[j*4+2], o16[j*4+3]);
        }
        __syncthreads();   // encoder gmem writes visible to whole CTA
    }

    for (int i = tid; i < 512; i += 256) {
        s_att[i]       = asrc[i];
        s_att[512 + i] = adst[i];
    }

    // A fill: 32 rows x 16 k-chunks = 512 tasks -> bf16 hi/lo swizzled
#pragma unroll
    for (int it = 0; it < 2; ++it) {
        int t = tid + 256 * it;
        int r = t >> 4, kb = t & 15;
        int il = r / 10, node = r - il * 10;
        long ig = blk * NI + il;
        uint32_t hi[4], lo[4];
        if (r < VROWS && ig < BT) {
            const float* src = nf_in + ig * NODE_F + node * HID + kb * 8;
            float4 a = *(const float4*)(src);
            float4 b = *(const float4*)(src + 4);
            split_bf16x2(a.x, a.y, hi[0], lo[0]);
            split_bf16x2(a.z, a.w, hi[1], lo[1]);
            split_bf16x2(b.x, b.y, hi[2], lo[2]);
            split_bf16x2(b.z, b.w, hi[3], lo[3]);
        } else {
#pragma unroll
            for (int j = 0; j < 4; ++j) { hi[j] = 0u; lo[j] = 0u; }
        }
        uint32_t off = (uint32_t)(r * 256 + ((kb ^ (r & 7)) * 16));
        *(uint4*)(smb + off)          = make_uint4(hi[0], hi[1], hi[2], hi[3]);
        *(uint4*)(smb + A_LO_B + off) = make_uint4(lo[0], lo[1], lo[2], lo[3]);
    }
    __syncthreads();

    const int q4 = lane >> 2;
    const int c2 = (lane & 3) * 2;

    // Hoisted A-fragment addressing
    const int m_  = lane >> 3, i2_ = lane & 7;
    const int kbh = m_ >> 1;
    const int rbase = (m_ & 1) * 8 + i2_;
    uint32_t arow[2], rx7[2];
#pragma unroll
    for (int mt = 0; mt < 2; ++mt) {
        int r = mt * 16 + rbase;
        arow[mt] = sb + (uint32_t)(r * 256);
        rx7[mt]  = (uint32_t)(r & 7);
    }

    // ---- GEMM: two 32-col sub-passes, acc register-local per pass ----
    float pals[2][2], pald[2][2];
    pals[0][0]=pals[0][1]=pals[1][0]=pals[1][1]=0.f;
    pald[0][0]=pald[0][1]=pald[1][0]=pald[1][1]=0.f;
    __half2* xph = s_xph + hh * XPH_U32;

#pragma unroll
    for (int s = 0; s < 2; ++s) {
        const uint4* Bw = (const uint4*)Wt + (hh * 4096 + (ch2 * 4 + s * 2) * 256 + lane);
        float acc[2][4][4];
#pragma unroll
        for (int mt = 0; mt < 2; ++mt)
#pragma unroll
            for (int n8 = 0; n8 < 4; ++n8)
#pragma unroll
                for (int j = 0; j < 4; ++j) acc[mt][n8][j] = 0.f;

#pragma unroll
        for (int kc = 0; kc < 8; ++kc) {
            const uint32_t kb = (uint32_t)(kc * 2 + kbh);
            uint32_t ahi[2][4], alo[2][4];
#pragma unroll
            for (int mt = 0; mt < 2; ++mt) {
                uint32_t addr = arow[mt] + ((kb ^ rx7[mt]) << 4);
                ldsm_x4(ahi[mt], addr);
                ldsm_x4(alo[mt], addr + A_LO_B);
            }
            uint4 b0 = Bw[kc * 32];
            uint4 b1 = Bw[kc * 32 + 256];
            uint4 l0 = Bw[kc * 32 + 2048];
            uint4 l1 = Bw[kc * 32 + 2304];
#pragma unroll
            for (int mt = 0; mt < 2; ++mt) {
                mma_bf16(acc[mt][0], ahi[mt], b0.x, b0.y);
                mma_bf16(acc[mt][1], ahi[mt], b0.z, b0.w);
                mma_bf16(acc[mt][2], ahi[mt], b1.x, b1.y);
                mma_bf16(acc[mt][3], ahi[mt], b1.z, b1.w);
                mma_bf16(acc[mt][0], alo[mt], b0.x, b0.y);
                mma_bf16(acc[mt][1], alo[mt], b0.z, b0.w);
                mma_bf16(acc[mt][2], alo[mt], b1.x, b1.y);
                mma_bf16(acc[mt][3], alo[mt], b1.z, b1.w);
                mma_bf16(acc[mt][0], ahi[mt], l0.x, l0.y);
                mma_bf16(acc[mt][1], ahi[mt], l0.z, l0.w);
                mma_bf16(acc[mt][2], ahi[mt], l1.x, l1.y);
                mma_bf16(acc[mt][3], ahi[mt], l1.z, l1.w);
            }
        }

        // xp store (half2) + logit partials from accumulators
#pragma unroll
        for (int mt = 0; mt < 2; ++mt) {
            int r0 = mt * 16 + q4;
#pragma unroll
            for (int n8 = 0; n8 < 4; ++n8) {
                int ch = ch2 * 64 + s * 32 + n8 * 8 + c2;
                float a0 = s_att[hh * 128 + ch],       a1 = s_att[hh * 128 + ch + 1];
                float d0 = s_att[512 + hh * 128 + ch], d1 = s_att[512 + hh * 128 + ch + 1];
                pals[mt][0] = fmaf(acc[mt][n8][0], a0, fmaf(acc[mt][n8][1], a1, pals[mt][0]));
                pald[mt][0] = fmaf(acc[mt][n8][0], d0, fmaf(acc[mt][n8][1], d1, pald[mt][0]));
                pals[mt][1] = fmaf(acc[mt][n8][2], a0, fmaf(acc[mt][n8][3], a1, pals[mt][1]));
                pald[mt][1] = fmaf(acc[mt][n8][2], d0, fmaf(acc[mt][n8][3], d1, pald[mt][1]));
                xph[r0 * XPS_U32 + (ch >> 1)]       = __floats2half2_rn(acc[mt][n8][0], acc[mt][n8][1]);
                xph[(r0 + 8) * XPS_U32 + (ch >> 1)] = __floats2half2_rn(acc[mt][n8][2], acc[mt][n8][3]);
            }
        }
    }

#pragma unroll
    for (int mt = 0; mt < 2; ++mt)
#pragma unroll
        for (int j = 0; j < 2; ++j) {
            pals[mt][j] += __shfl_xor_sync(0xffffffffu, pals[mt][j], 1);
            pals[mt][j] += __shfl_xor_sync(0xffffffffu, pals[mt][j], 2);
            pald[mt][j] += __shfl_xor_sync(0xffffffffu, pald[mt][j], 1);
            pald[mt][j] += __shfl_xor_sync(0xffffffffu, pald[mt][j], 2);
        }
    if ((lane & 3) == 0) {
#pragma unroll
        for (int mt = 0; mt < 2; ++mt) {
            int r0 = mt * 16 + q4;
            s_alsp[wid * 32 + r0]     = pals[mt][0];
            s_alsp[wid * 32 + r0 + 8] = pals[mt][1];
            s_aldp[wid * 32 + r0]     = pald[mt][0];
            s_aldp[wid * 32 + r0 + 8] = pald[mt][1];
        }
    }
    __syncthreads();

    // ---- segment softmax (120 workers: 4 heads x 3 inst x 10 dst) ----
    if (tid < 120) {
        int th = tid / 30, rem = tid - th * 30;
        int il = rem / 10, dst = rem - il * 10, rb = il * 10;
        const float* asl = s_alsp + th * 64;
        const float* adl = s_aldp + th * 64;
        int rd = rb + dst;
        float ald = adl[rd] + adl[32 + rd];
        int s0 = c_start[dst], s1 = c_start[dst + 1];
        float vb[5], m = -1e30f;
        for (int k = s0; k < s1; ++k) {
            int rs = rb + c_src[k];
            float als = asl[rs] + asl[32 + rs];
            float v = als + ald;
            v = v > 0.f ? v : 0.2f * v;
            vb[k - s0] = v;
            m = fmaxf(m, v);
        }
        float ssum = 0.f;
        for (int k = s0; k < s1; ++k) {
            float ex = __expf(vb[k - s0] - m);
            ssum += ex;
            s_alpha[(th * 3 + il) * NE + k] = ex;
        }
        float inv = 1.0f / ssum;
        for (int k = s0; k < s1; ++k) s_alpha[(th * 3 + il) * NE + k] *= inv;
    }
    __syncthreads();

    // ---- fused aggregation (all heads) + mean + bias + GELU + residual ----
#pragma unroll
    for (int it = 0; it < 4; ++it) {
        int q = tid + 256 * it;                 // 960 float4 tasks
        if (q < 960) {
            int il = q / 320, rem = q - il * 320, dst = rem >> 5, f = (rem & 31) * 4;
            long ig = blk * NI + il;
            if (ig < BT) {
                int rb = il * 10;
                int s0 = c_start[dst], s1 = c_start[dst + 1];
                float4 a4; a4.x = a4.y = a4.z = a4.w = 0.f;
#pragma unroll
                for (int th = 0; th < 4; ++th) {
                    const float* al = s_alpha + (th * 3 + il) * NE;
                    const uint2* xb = (const uint2*)(s_xph + th * XPH_U32 + (f >> 1));
                    for (int k = s0; k < s1; ++k) {
                        int row = rb + c_src[k];
                        float a = al[k];
                        uint2 p = xb[row * (XPS_U32 / 2)];
                        float2 f0 = __half22float2(*(__half2*)&p.x);
                        float2 f1 = __half22float2(*(__half2*)&p.y);
                        a4.x = fmaf(a, f0.x, a4.x);
                        a4.y = fmaf(a, f0.y, a4.y);
                        a4.z = fmaf(a, f1.x, a4.z);
                        a4.w = fmaf(a, f1.y, a4.w);
                    }
                }
                float4 bgv = *(const float4*)(bg + f);
                float4 rs  = *(const float4*)(nf_in + ig * NODE_F + dst * HID + f);
                float4 w;
                w.x = gelu_exact(fmaf(0.25f, a4.x, bgv.x)) + rs.x;
                w.y = gelu_exact(fmaf(0.25f, a4.y, bgv.y)) + rs.y;
                w.z = gelu_exact(fmaf(0.25f, a4.z, bgv.z)) + rs.z;
                w.w = gelu_exact(fmaf(0.25f, a4.w, bgv.w)) + rs.w;
                *(float4*)(nf_out + ig * NODE_F + dst * HID + f) = w;
            }
        }
    }
}

// ---------------------------------------------------------------------------
extern "C" void kernel_launch(void* const* d_in, const int* in_sizes, int n_in,
                              void* d_out, int out_size)
{
    const float* x     = (const float*)d_in[0];
    const float* Wenc  = (const float*)d_in[1];
    const float* benc  = (const float*)d_in[2];
    const float* gamma = (const float*)d_in[3];
    const float* beta  = (const float*)d_in[4];
    const float* Wg    = (const float*)d_in[5];
    const float* asrc  = (const float*)d_in[6];
    const float* adst  = (const float*)d_in[7];
    const float* bg    = (const float*)d_in[8];

    float* out = (float*)d_out;

    float* nf0;  cudaGetSymbolAddress((void**)&nf0, g_nf0);
    float* nf1;  cudaGetSymbolAddress((void**)&nf1, g_nf1);
    uint8_t* wt; cudaGetSymbolAddress((void**)&wt, g_Wt);

    // region_feats buffer: required second output when present, else scratch.
    float* reg = (out_size >= 2 * NTOT) ? out + NTOT : nf0;
    float* buf1 = nf1;
    float* buf2 = (reg == nf0) ? nf0 : nf0;   // layer-1 output buffer (nf0 is free either way after l0 input is reg? l0 input IS reg)
    // Safe chain: l0: reg -> nf1 ; l1: nf1 -> nf0 (nf0 only aliases reg when
    // region output is absent, in which case reg is no longer needed) ; l2: nf0 -> out.

    cudaFuncSetAttribute(gat_mma_kernel<true>,  cudaFuncAttributeMaxDynamicSharedMemorySize, SM_DYNBYTES);
    cudaFuncSetAttribute(gat_mma_kernel<false>, cudaFuncAttributeMaxDynamicSharedMemorySize, SM_DYNBYTES);

    wt_kernel<<<12, 256>>>(Wg);
    gat_mma_kernel<true><<<GRID_GAT, 256, SM_DYNBYTES>>>(
        x, Wenc, benc, gamma, beta, reg, wt,              asrc,        adst,        bg,       buf1);
    gat_mma_kernel<false><<<GRID_GAT, 256, SM_DYNBYTES>>>(
        nullptr, nullptr, nullptr, nullptr, nullptr, buf1, wt + 4 * 65536, asrc + 512,  adst + 512,  bg + 128, buf2);
    gat_mma_kernel<false><<<GRID_GAT, 256, SM_DYNBYTES>>>(
        nullptr, nullptr, nullptr, nullptr, nullptr, buf2, wt + 8 * 65536, asrc + 1024, adst + 1024, bg + 256, out);
}

// round 16
// speedup vs baseline: 1.3330x; 1.3330x over previous
#include <cuda_runtime.h>
#include <cuda_bf16.h>
#include <cuda_fp16.h>
#include <math.h>
#include <stdint.h>

// Problem constants
#define R_NODES 10
#define HID 128
#define NE 36
#define BT 12800
#define NODE_F 1280
#define NTOT (BT * NODE_F)
#define LN_EPS 1e-5f
#define NI 3
#define VROWS 30
#define GRID_GAT ((BT + NI - 1) / NI)   // 4267

__device__ float g_nf0[NTOT];
__device__ float g_nf1[NTOT];
// W pre-arranged in mma.sync B-fragment layout:
// [layer][head]{ hi: [wslot(8)][kc(8)][lane(32)] 16B chunks = 32KB, lo: +32KB }
__device__ __align__(16) uint8_t g_Wt[3 * 4 * 65536];

__constant__ int c_start[R_NODES + 1] = {0, 5, 8, 12, 15, 17, 22, 27, 31, 33, 36};
__constant__ int c_src[NE] = {
    9, 5, 6, 1, 0,   0, 2, 1,   5, 1, 3, 2,   2, 4, 3,   3, 4,
    6, 2, 0, 7, 5,   5, 9, 0, 7, 6,   6, 5, 8, 7,   7, 8,   6, 0, 9
};

// Fast erf (Abramowitz-Stegun 7.1.26, |abs err| <= 1.5e-7)
__device__ __forceinline__ float erf_fast(float x) {
    float ax = fabsf(x);
    float t = 1.0f / fmaf(0.3275911f, ax, 1.0f);
    float y = t * fmaf(t, fmaf(t, fmaf(t, fmaf(t, 1.061405429f, -1.453152027f),
                                       1.421413741f), -0.284496736f), 0.254829592f);
    float r = 1.0f - y * __expf(-ax * ax);
    return copysignf(r, x);
}
__device__ __forceinline__ float gelu_exact(float v) {
    return 0.5f * v * (1.0f + erf_fast(v * 0.70710678118654752440f));
}
__device__ __forceinline__ uint32_t smem_u32(const void* p) {
    uint32_t a;
    asm("{ .reg .u64 t; cvta.to.shared.u64 t, %1; cvt.u32.u64 %0, t; }" : "=r"(a) : "l"(p));
    return a;
}
__device__ __forceinline__ void ldsm_x4(uint32_t* r, uint32_t addr) {
    asm volatile("ldmatrix.sync.aligned.m8n8.x4.shared.b16 {%0,%1,%2,%3}, [%4];"
                 : "=r"(r[0]), "=r"(r[1]), "=r"(r[2]), "=r"(r[3]) : "r"(addr));
}
__device__ __forceinline__ void mma_bf16(float* d, const uint32_t* a, uint32_t b0, uint32_t b1) {
    asm volatile("mma.sync.aligned.m16n8k16.row.col.f32.bf16.bf16.f32 "
                 "{%0,%1,%2,%3}, {%4,%5,%6,%7}, {%8,%9}, {%0,%1,%2,%3};"
                 : "+f"(d[0]), "+f"(d[1]), "+f"(d[2]), "+f"(d[3])
                 : "r"(a[0]), "r"(a[1]), "r"(a[2]), "r"(a[3]), "r"(b0), "r"(b1));
}
__device__ __forceinline__ void split_bf16x2(float v0, float v1, uint32_t& hi, uint32_t& lo) {
    __nv_bfloat16 h0 = __float2bfloat16(v0);
    __nv_bfloat16 h1 = __float2bfloat16(v1);
    __nv_bfloat16 l0 = __float2bfloat16(v0 - __bfloat162float(h0));
    __nv_bfloat16 l1 = __float2bfloat16(v1 - __bfloat162float(h1));
    hi = (uint32_t)__bfloat16_as_ushort(h0) | ((uint32_t)__bfloat16_as_ushort(h1) << 16);
    lo = (uint32_t)__bfloat16_as_ushort(l0) | ((uint32_t)__bfloat16_as_ushort(l1) << 16);
}

// ---------------------------------------------------------------------------
// Fused W-prep (blocks 0..11) + encoder (blocks 12..6411)
// ---------------------------------------------------------------------------
__global__ void __launch_bounds__(256) wt_enc_kernel(
    const float* __restrict__ Wg,
    const float* __restrict__ x, const float* __restrict__ Wenc,
    const float* __restrict__ benc, const float* __restrict__ gamma,
    const float* __restrict__ beta, float* __restrict__ nf_out,
    float* __restrict__ region_out)
{
    if (blockIdx.x < 12) {
        // ---- W prep ----
        int l = blockIdx.x >> 2, h = blockIdx.x & 3;
        uint8_t* base = g_Wt + (size_t)(l * 4 + h) * 65536;
        const float* W = Wg + l * 65536 + h * 128;   // W[k*512 + n]
        for (int c = threadIdx.x; c < 2048; c += 256) {
            int ws = c >> 8, kc = (c >> 5) & 7, lane = c & 31;
            int n0 = ws * 16 + (lane >> 2);
            int k0 = kc * 16 + 2 * (lane & 3);
            uint32_t hi[4], lo[4];
#pragma unroll
            for (int j = 0; j < 4; ++j) {
                int n = n0 + (j >> 1) * 8;
                int k = k0 + (j & 1) * 8;
                float w0 = W[k * 512 + n];
                float w1 = W[(k + 1) * 512 + n];
                split_bf16x2(w0, w1, hi[j], lo[j]);
            }
            *(uint4*)(base + c * 16)         = make_uint4(hi[0], hi[1], hi[2], hi[3]);
            *(uint4*)(base + 32768 + c * 16) = make_uint4(lo[0], lo[1], lo[2], lo[3]);
        }
        return;
    }
    // ---- encoder: 2 instances per block ----
    const int tid = threadIdx.x;
    const int lane = tid & 31;
    const int w4 = (tid >> 5) & 3;
    const int inst = tid >> 7;
    const long bt = (long)(blockIdx.x - 12) * 2 + inst;
    const float* xr = x + bt * (R_NODES * 6);
    float* outp = nf_out + bt * NODE_F;
    float* regp = region_out ? region_out + bt * NODE_F : nullptr;

    for (int r = w4; r < R_NODES; r += 4) {
        float xv[6];
#pragma unroll
        for (int c = 0; c < 6; ++c) xv[c] = xr[r * 6 + c];
        float h[4];
#pragma unroll
        for (int j = 0; j < 4; ++j) {
            int k = lane + 32 * j;
            float a = benc[r * HID + k];
#pragma unroll
            for (int c = 0; c < 6; ++c) a = fmaf(xv[c], Wenc[(r * 6 + c) * HID + k], a);
            h[j] = a;
        }
        float s = h[0] + h[1] + h[2] + h[3];
        float sq = h[0]*h[0] + h[1]*h[1] + h[2]*h[2] + h[3]*h[3];
#pragma unroll
        for (int o = 16; o > 0; o >>= 1) {
            s  += __shfl_xor_sync(0xffffffffu, s, o);
            sq += __shfl_xor_sync(0xffffffffu, sq, o);
        }
        float mean = s * (1.0f / 128.0f);
        float var = sq * (1.0f / 128.0f) - mean * mean;
        float rstd = rsqrtf(var + LN_EPS);
#pragma unroll
        for (int j = 0; j < 4; ++j) {
            int k = lane + 32 * j;
            float v = (h[j] - mean) * rstd * gamma[r * HID + k] + beta[r * HID + k];
            float g = gelu_exact(v);
            outp[r * HID + k] = g;
            if (regp) regp[r * HID + k] = g;
        }
    }
}

// ---------------------------------------------------------------------------
// GAT layer (R12 structure) with head-interleaved xp:
//   xp u32 index = row*264 + col_pair*4 + head   (half2 per entry)
// Aggregation reads all 4 heads with 2x uint4 + 1x float4(alpha) per edge.
// smem byte map (58048, 3 CTAs/SM):
//   0      A_hi (8192)      8192   A_lo (8192)
//   16384  xp   [32][264 u32] = 33792
//   50176  att  (4096)
//   54272  alsp (1024)      55296  aldp (1024)
//   56320  alpha [3][36][4] floats = 1728
// ---------------------------------------------------------------------------
#define A_LO_B   8192
#define XP_B     16384
#define XPS_U32  264
#define ATT_B    50176
#define ALSP_B   54272
#define ALDP_B   55296
#define ALPHA_B  56320
#define SM_DYNBYTES 58048

__global__ void __launch_bounds__(256, 3) gat_mma_kernel(
    const float* __restrict__ nf_in, const uint8_t* __restrict__ Wt,
    const float* __restrict__ asrc, const float* __restrict__ adst,
    const float* __restrict__ bg, float* __restrict__ nf_out)
{
    extern __shared__ uint8_t smb[];
    const uint32_t sb = smem_u32(smb);
    uint32_t* s_xpu = (uint32_t*)(smb + XP_B);
    float* s_att   = (float*)(smb + ATT_B);
    float* s_alsp  = (float*)(smb + ALSP_B);
    float* s_aldp  = (float*)(smb + ALDP_B);
    float* s_alpha = (float*)(smb + ALPHA_B);

    const int tid  = threadIdx.x;
    const int wid  = tid >> 5;
    const int lane = tid & 31;
    const int hh   = wid >> 1;          // head 0..3
    const int ch2  = wid & 1;           // col half within head
    const long blk = blockIdx.x;

    for (int i = tid; i < 512; i += 256) {
        s_att[i]       = asrc[i];
        s_att[512 + i] = adst[i];
    }

    // A fill: 32 rows x 16 k-chunks = 512 tasks -> bf16 hi/lo swizzled
#pragma unroll
    for (int it = 0; it < 2; ++it) {
        int t = tid + 256 * it;
        int r = t >> 4, kb = t & 15;
        int il = r / 10, node = r - il * 10;
        long ig = blk * NI + il;
        uint32_t hi[4], lo[4];
        if (r < VROWS && ig < BT) {
            const float* src = nf_in + ig * NODE_F + node * HID + kb * 8;
            float4 a = *(const float4*)(src);
            float4 b = *(const float4*)(src + 4);
            split_bf16x2(a.x, a.y, hi[0], lo[0]);
            split_bf16x2(a.z, a.w, hi[1], lo[1]);
            split_bf16x2(b.x, b.y, hi[2], lo[2]);
            split_bf16x2(b.z, b.w, hi[3], lo[3]);
        } else {
#pragma unroll
            for (int j = 0; j < 4; ++j) { hi[j] = 0u; lo[j] = 0u; }
        }
        uint32_t off = (uint32_t)(r * 256 + ((kb ^ (r & 7)) * 16));
        *(uint4*)(smb + off)          = make_uint4(hi[0], hi[1], hi[2], hi[3]);
        *(uint4*)(smb + A_LO_B + off) = make_uint4(lo[0], lo[1], lo[2], lo[3]);
    }
    __syncthreads();

    const int q4 = lane >> 2;
    const int c2 = (lane & 3) * 2;

    // Hoisted A-fragment addressing
    const int m_  = lane >> 3, i2_ = lane & 7;
    const int kbh = m_ >> 1;
    const int rbase = (m_ & 1) * 8 + i2_;
    uint32_t arow[2], rx7[2];
#pragma unroll
    for (int mt = 0; mt < 2; ++mt) {
        int r = mt * 16 + rbase;
        arow[mt] = sb + (uint32_t)(r * 256);
        rx7[mt]  = (uint32_t)(r & 7);
    }

    // ---- GEMM: two 32-col sub-passes, acc register-local per pass ----
    float pals[2][2], pald[2][2];
    pals[0][0]=pals[0][1]=pals[1][0]=pals[1][1]=0.f;
    pald[0][0]=pald[0][1]=pald[1][0]=pald[1][1]=0.f;

#pragma unroll
    for (int s = 0; s < 2; ++s) {
        const uint4* Bw = (const uint4*)Wt + (hh * 4096 + (ch2 * 4 + s * 2) * 256 + lane);
        float acc[2][4][4];
#pragma unroll
        for (int mt = 0; mt < 2; ++mt)
#pragma unroll
            for (int n8 = 0; n8 < 4; ++n8)
#pragma unroll
                for (int j = 0; j < 4; ++j) acc[mt][n8][j] = 0.f;

#pragma unroll
        for (int kc = 0; kc < 8; ++kc) {
            const uint32_t kb = (uint32_t)(kc * 2 + kbh);
            uint32_t ahi[2][4], alo[2][4];
#pragma unroll
            for (int mt = 0; mt < 2; ++mt) {
                uint32_t addr = arow[mt] + ((kb ^ rx7[mt]) << 4);
                ldsm_x4(ahi[mt], addr);
                ldsm_x4(alo[mt], addr + A_LO_B);
            }
            uint4 b0 = Bw[kc * 32];
            uint4 b1 = Bw[kc * 32 + 256];
            uint4 l0 = Bw[kc * 32 + 2048];
            uint4 l1 = Bw[kc * 32 + 2304];
#pragma unroll
            for (int mt = 0; mt < 2; ++mt) {
                mma_bf16(acc[mt][0], ahi[mt], b0.x, b0.y);
                mma_bf16(acc[mt][1], ahi[mt], b0.z, b0.w);
                mma_bf16(acc[mt][2], ahi[mt], b1.x, b1.y);
                mma_bf16(acc[mt][3], ahi[mt], b1.z, b1.w);
                mma_bf16(acc[mt][0], alo[mt], b0.x, b0.y);
                mma_bf16(acc[mt][1], alo[mt], b0.z, b0.w);
                mma_bf16(acc[mt][2], alo[mt], b1.x, b1.y);
                mma_bf16(acc[mt][3], alo[mt], b1.z, b1.w);
                mma_bf16(acc[mt][0], ahi[mt], l0.x, l0.y);
                mma_bf16(acc[mt][1], ahi[mt], l0.z, l0.w);
                mma_bf16(acc[mt][2], ahi[mt], l1.x, l1.y);
                mma_bf16(acc[mt][3], ahi[mt], l1.z, l1.w);
            }
        }

        // xp store (half2, head-interleaved) + logit partials from accumulators
#pragma unroll
        for (int mt = 0; mt < 2; ++mt) {
            int r0 = mt * 16 + q4;
#pragma unroll
            for (int n8 = 0; n8 < 4; ++n8) {
                int cp = ch2 * 32 + s * 16 + n8 * 4 + (lane & 3);   // col pair
                int ch = cp * 2;                                     // col within head
                float a0 = s_att[hh * 128 + ch],       a1 = s_att[hh * 128 + ch + 1];
                float d0 = s_att[512 + hh * 128 + ch], d1 = s_att[512 + hh * 128 + ch + 1];
                pals[mt][0] = fmaf(acc[mt][n8][0], a0, fmaf(acc[mt][n8][1], a1, pals[mt][0]));
                pald[mt][0] = fmaf(acc[mt][n8][0], d0, fmaf(acc[mt][n8][1], d1, pald[mt][0]));
                pals[mt][1] = fmaf(acc[mt][n8][2], a0, fmaf(acc[mt][n8][3], a1, pals[mt][1]));
                pald[mt][1] = fmaf(acc[mt][n8][2], d0, fmaf(acc[mt][n8][3], d1, pald[mt][1]));
                __half2 v0 = __floats2half2_rn(acc[mt][n8][0], acc[mt][n8][1]);
                __half2 v1 = __floats2half2_rn(acc[mt][n8][2], acc[mt][n8][3]);
                s_xpu[r0 * XPS_U32 + cp * 4 + hh]       = *(uint32_t*)&v0;
                s_xpu[(r0 + 8) * XPS_U32 + cp * 4 + hh] = *(uint32_t*)&v1;
            }
        }
    }

#pragma unroll
    for (int mt = 0; mt < 2; ++mt)
#pragma unroll
        for (int j = 0; j < 2; ++j) {
            pals[mt][j] += __shfl_xor_sync(0xffffffffu, pals[mt][j], 1);
            pals[mt][j] += __shfl_xor_sync(0xffffffffu, pals[mt][j], 2);
            pald[mt][j] += __shfl_xor_sync(0xffffffffu, pald[mt][j], 1);
            pald[mt][j] += __shfl_xor_sync(0xffffffffu, pald[mt][j], 2);
        }
    if ((lane & 3) == 0) {
#pragma unroll
        for (int mt = 0; mt < 2; ++mt) {
            int r0 = mt * 16 + q4;
            s_alsp[wid * 32 + r0]     = pals[mt][0];
            s_alsp[wid * 32 + r0 + 8] = pals[mt][1];
            s_aldp[wid * 32 + r0]     = pald[mt][0];
            s_aldp[wid * 32 + r0 + 8] = pald[mt][1];
        }
    }
    __syncthreads();

    // ---- segment softmax (120 workers: 4 heads x 3 inst x 10 dst) ----
    if (tid < 120) {
        int th = tid / 30, rem = tid - th * 30;
        int il = rem / 10, dst = rem - il * 10, rb = il * 10;
        const float* asl = s_alsp + th * 64;
        const float* adl = s_aldp + th * 64;
        int rd = rb + dst;
        float ald = adl[rd] + adl[32 + rd];
        int s0 = c_start[dst], s1 = c_start[dst + 1];
        float vb[5], m = -1e30f;
        for (int k = s0; k < s1; ++k) {
            int rs = rb + c_src[k];
            float als = asl[rs] + asl[32 + rs];
            float v = als + ald;
            v = v > 0.f ? v : 0.2f * v;
            vb[k - s0] = v;
            m = fmaxf(m, v);
        }
        float ssum = 0.f;
        float eb[5];
        for (int k = s0; k < s1; ++k) {
            float ex = __expf(vb[k - s0] - m);
            ssum += ex;
            eb[k - s0] = ex;
        }
        float inv = 1.0f / ssum;
        for (int k = s0; k < s1; ++k)
            s_alpha[(il * NE + k) * 4 + th] = eb[k - s0] * inv;
    }
    __syncthreads();

    // ---- fused aggregation (all heads at once) + mean + bias + GELU + residual ----
#pragma unroll
    for (int it = 0; it < 4; ++it) {
        int q = tid + 256 * it;                 // 960 float4 tasks
        if (q < 960) {
            int il = q / 320, rem = q - il * 320, dst = rem >> 5, f = (rem & 31) * 4;
            long ig = blk * NI + il;
            if (ig < BT) {
                int rb = il * 10;
                int s0 = c_start[dst], s1 = c_start[dst + 1];
                const uint32_t* xb = s_xpu + (f >> 1) * 4;
                float4 a4; a4.x = a4.y = a4.z = a4.w = 0.f;
                for (int k = s0; k < s1; ++k) {
                    int row = rb + c_src[k];
                    float4 al4 = *(const float4*)(s_alpha + (il * NE + k) * 4);
                    const uint32_t* p = xb + row * XPS_U32;
                    uint4 u0 = *(const uint4*)(p);       // heads 0..3, cols f,f+1
                    uint4 u1 = *(const uint4*)(p + 4);   // heads 0..3, cols f+2,f+3
                    float2 c0, c1;
                    c0 = __half22float2(*(__half2*)&u0.x); c1 = __half22float2(*(__half2*)&u1.x);
                    a4.x = fmaf(al4.x, c0.x, a4.x); a4.y = fmaf(al4.x, c0.y, a4.y);
                    a4.z = fmaf(al4.x, c1.x, a4.z); a4.w = fmaf(al4.x, c1.y, a4.w);
                    c0 = __half22float2(*(__half2*)&u0.y); c1 = __half22float2(*(__half2*)&u1.y);
                    a4.x = fmaf(al4.y, c0.x, a4.x); a4.y = fmaf(al4.y, c0.y, a4.y);
                    a4.z = fmaf(al4.y, c1.x, a4.z); a4.w = fmaf(al4.y, c1.y, a4.w);
                    c0 = __half22float2(*(__half2*)&u0.z); c1 = __half22float2(*(__half2*)&u1.z);
                    a4.x = fmaf(al4.z, c0.x, a4.x); a4.y = fmaf(al4.z, c0.y, a4.y);
                    a4.z = fmaf(al4.z, c1.x, a4.z); a4.w = fmaf(al4.z, c1.y, a4.w);
                    c0 = __half22float2(*(__half2*)&u0.w); c1 = __half22float2(*(__half2*)&u1.w);
                    a4.x = fmaf(al4.w, c0.x, a4.x); a4.y = fmaf(al4.w, c0.y, a4.y);
                    a4.z = fmaf(al4.w, c1.x, a4.z); a4.w = fmaf(al4.w, c1.y, a4.w);
                }
                float4 bgv = *(const float4*)(bg + f);
                float4 rs  = *(const float4*)(nf_in + ig * NODE_F + dst * HID + f);
                float4 w;
                w.x = gelu_exact(fmaf(0.25f, a4.x, bgv.x)) + rs.x;
                w.y = gelu_exact(fmaf(0.25f, a4.y, bgv.y)) + rs.y;
                w.z = gelu_exact(fmaf(0.25f, a4.z, bgv.z)) + rs.z;
                w.w = gelu_exact(fmaf(0.25f, a4.w, bgv.w)) + rs.w;
                *(float4*)(nf_out + ig * NODE_F + dst * HID + f) = w;
            }
        }
    }
}

// ---------------------------------------------------------------------------
extern "C" void kernel_launch(void* const* d_in, const int* in_sizes, int n_in,
                              void* d_out, int out_size)
{
    const float* x     = (const float*)d_in[0];
    const float* Wenc  = (const float*)d_in[1];
    const float* benc  = (const float*)d_in[2];
    const float* gamma = (const float*)d_in[3];
    const float* beta  = (const float*)d_in[4];
    const float* Wg    = (const float*)d_in[5];
    const float* asrc  = (const float*)d_in[6];
    const float* adst  = (const float*)d_in[7];
    const float* bg    = (const float*)d_in[8];

    float* out = (float*)d_out;
    float* region_out = (out_size >= 2 * NTOT) ? out + NTOT : nullptr;

    float* nf0;  cudaGetSymbolAddress((void**)&nf0, g_nf0);
    float* nf1;  cudaGetSymbolAddress((void**)&nf1, g_nf1);
    uint8_t* wt; cudaGetSymbolAddress((void**)&wt, g_Wt);

    cudaFuncSetAttribute(gat_mma_kernel, cudaFuncAttributeMaxDynamicSharedMemorySize, SM_DYNBYTES);

    wt_enc_kernel<<<12 + BT / 2, 256>>>(Wg, x, Wenc, benc, gamma, beta, nf0, region_out);

    gat_mma_kernel<<<GRID_GAT, 256, SM_DYNBYTES>>>(nf0, wt,               asrc,        adst,        bg,       nf1);
    gat_mma_kernel<<<GRID_GAT, 256, SM_DYNBYTES>>>(nf1, wt + 4 * 65536,   asrc + 512,  adst + 512,  bg + 128, nf0);
    gat_mma_kernel<<<GRID_GAT, 256, SM_DYNBYTES>>>(nf0, wt + 8 * 65536,   asrc + 1024, adst + 1024, bg + 256, out);
}

// round 17
// speedup vs baseline: 1.3867x; 1.0403x over previous
#include <cuda_runtime.h>
#include <cuda_bf16.h>
#include <cuda_fp16.h>
#include <math.h>
#include <stdint.h>

// Problem constants
#define R_NODES 10
#define HID 128
#define NE 36
#define BT 12800
#define NODE_F 1280
#define NTOT (BT * NODE_F)
#define LN_EPS 1e-5f
#define NI 3
#define VROWS 30
#define GRID_GAT ((BT + NI - 1) / NI)   // 4267

__device__ float g_nf0[NTOT];
__device__ float g_nf1[NTOT];
// W pre-arranged in mma.sync B-fragment layout:
// [layer][head]{ hi: [wslot(8)][kc(8)][lane(32)] 16B chunks = 32KB, lo: +32KB }
__device__ __align__(16) uint8_t g_Wt[3 * 4 * 65536];

__constant__ int c_start[R_NODES + 1] = {0, 5, 8, 12, 15, 17, 22, 27, 31, 33, 36};
__constant__ int c_src[NE] = {
    9, 5, 6, 1, 0,   0, 2, 1,   5, 1, 3, 2,   2, 4, 3,   3, 4,
    6, 2, 0, 7, 5,   5, 9, 0, 7, 6,   6, 5, 8, 7,   7, 8,   6, 0, 9
};

// Fast erf (Abramowitz-Stegun 7.1.26, |abs err| <= 1.5e-7)
__device__ __forceinline__ float erf_fast(float x) {
    float ax = fabsf(x);
    float t = 1.0f / fmaf(0.3275911f, ax, 1.0f);
    float y = t * fmaf(t, fmaf(t, fmaf(t, fmaf(t, 1.061405429f, -1.453152027f),
                                       1.421413741f), -0.284496736f), 0.254829592f);
    float r = 1.0f - y * __expf(-ax * ax);
    return copysignf(r, x);
}
__device__ __forceinline__ float gelu_exact(float v) {
    return 0.5f * v * (1.0f + erf_fast(v * 0.70710678118654752440f));
}
__device__ __forceinline__ uint32_t smem_u32(const void* p) {
    uint32_t a;
    asm("{ .reg .u64 t; cvta.to.shared.u64 t, %1; cvt.u32.u64 %0, t; }" : "=r"(a) : "l"(p));
    return a;
}
__device__ __forceinline__ void ldsm_x4(uint32_t* r, uint32_t addr) {
    asm volatile("ldmatrix.sync.aligned.m8n8.x4.shared.b16 {%0,%1,%2,%3}, [%4];"
                 : "=r"(r[0]), "=r"(r[1]), "=r"(r[2]), "=r"(r[3]) : "r"(addr));
}
__device__ __forceinline__ void mma_bf16(float* d, const uint32_t* a, uint32_t b0, uint32_t b1) {
    asm volatile("mma.sync.aligned.m16n8k16.row.col.f32.bf16.bf16.f32 "
                 "{%0,%1,%2,%3}, {%4,%5,%6,%7}, {%8,%9}, {%0,%1,%2,%3};"
                 : "+f"(d[0]), "+f"(d[1]), "+f"(d[2]), "+f"(d[3])
                 : "r"(a[0]), "r"(a[1]), "r"(a[2]), "r"(a[3]), "r"(b0), "r"(b1));
}
__device__ __forceinline__ void split_bf16x2(float v0, float v1, uint32_t& hi, uint32_t& lo) {
    __nv_bfloat16 h0 = __float2bfloat16(v0);
    __nv_bfloat16 h1 = __float2bfloat16(v1);
    __nv_bfloat16 l0 = __float2bfloat16(v0 - __bfloat162float(h0));
    __nv_bfloat16 l1 = __float2bfloat16(v1 - __bfloat162float(h1));
    hi = (uint32_t)__bfloat16_as_ushort(h0) | ((uint32_t)__bfloat16_as_ushort(h1) << 16);
    lo = (uint32_t)__bfloat16_as_ushort(l0) | ((uint32_t)__bfloat16_as_ushort(l1) << 16);
}

// ---------------------------------------------------------------------------
// Fused W-prep (blocks 0..11) + encoder (blocks 12..6411)
// ---------------------------------------------------------------------------
__global__ void __launch_bounds__(256) wt_enc_kernel(
    const float* __restrict__ Wg,
    const float* __restrict__ x, const float* __restrict__ Wenc,
    const float* __restrict__ benc, const float* __restrict__ gamma,
    const float* __restrict__ beta, float* __restrict__ nf_out,
    float* __restrict__ region_out)
{
    if (blockIdx.x < 12) {
        int l = blockIdx.x >> 2, h = blockIdx.x & 3;
        uint8_t* base = g_Wt + (size_t)(l * 4 + h) * 65536;
        const float* W = Wg + l * 65536 + h * 128;   // W[k*512 + n]
        for (int c = threadIdx.x; c < 2048; c += 256) {
            int ws = c >> 8, kc = (c >> 5) & 7, lane = c & 31;
            int n0 = ws * 16 + (lane >> 2);
            int k0 = kc * 16 + 2 * (lane & 3);
            uint32_t hi[4], lo[4];
#pragma unroll
            for (int j = 0; j < 4; ++j) {
                int n = n0 + (j >> 1) * 8;
                int k = k0 + (j & 1) * 8;
                float w0 = W[k * 512 + n];
                float w1 = W[(k + 1) * 512 + n];
                split_bf16x2(w0, w1, hi[j], lo[j]);
            }
            *(uint4*)(base + c * 16)         = make_uint4(hi[0], hi[1], hi[2], hi[3]);
            *(uint4*)(base + 32768 + c * 16) = make_uint4(lo[0], lo[1], lo[2], lo[3]);
        }
        return;
    }
    const int tid = threadIdx.x;
    const int lane = tid & 31;
    const int w4 = (tid >> 5) & 3;
    const int inst = tid >> 7;
    const long bt = (long)(blockIdx.x - 12) * 2 + inst;
    const float* xr = x + bt * (R_NODES * 6);
    float* outp = nf_out + bt * NODE_F;
    float* regp = region_out ? region_out + bt * NODE_F : nullptr;

    for (int r = w4; r < R_NODES; r += 4) {
        float xv[6];
#pragma unroll
        for (int c = 0; c < 6; ++c) xv[c] = xr[r * 6 + c];
        float h[4];
#pragma unroll
        for (int j = 0; j < 4; ++j) {
            int k = lane + 32 * j;
            float a = benc[r * HID + k];
#pragma unroll
            for (int c = 0; c < 6; ++c) a = fmaf(xv[c], Wenc[(r * 6 + c) * HID + k], a);
            h[j] = a;
        }
        float s = h[0] + h[1] + h[2] + h[3];
        float sq = h[0]*h[0] + h[1]*h[1] + h[2]*h[2] + h[3]*h[3];
#pragma unroll
        for (int o = 16; o > 0; o >>= 1) {
            s  += __shfl_xor_sync(0xffffffffu, s, o);
            sq += __shfl_xor_sync(0xffffffffu, sq, o);
        }
        float mean = s * (1.0f / 128.0f);
        float var = sq * (1.0f / 128.0f) - mean * mean;
        float rstd = rsqrtf(var + LN_EPS);
#pragma unroll
        for (int j = 0; j < 4; ++j) {
            int k = lane + 32 * j;
            float v = (h[j] - mean) * rstd * gamma[r * HID + k] + beta[r * HID + k];
            float g = gelu_exact(v);
            outp[r * HID + k] = g;
            if (regp) regp[r * HID + k] = g;
        }
    }
}

// ---------------------------------------------------------------------------
// GAT layer: per-head xp planes (stride 66 u32), uint2 aggregation loads,
// alpha [edge][head] float4, float2 att loads. 3 inst/CTA, 3 CTAs/SM.
// smem byte map (58048):
//   0      A_hi (8192)      8192   A_lo (8192)
//   16384  xp   [4][32][66 u32] = 33792
//   50176  att  (4096)
//   54272  alsp (1024)      55296  aldp (1024)
//   56320  alpha [3][36][4] floats = 1728
// ---------------------------------------------------------------------------
#define A_LO_B   8192
#define XP_B     16384
#define XPS_U32  66
#define XPH_U32  (32 * XPS_U32)
#define ATT_B    50176
#define ALSP_B   54272
#define ALDP_B   55296
#define ALPHA_B  56320
#define SM_DYNBYTES 58048

__global__ void __launch_bounds__(256, 3) gat_mma_kernel(
    const float* __restrict__ nf_in, const uint8_t* __restrict__ Wt,
    const float* __restrict__ asrc, const float* __restrict__ adst,
    const float* __restrict__ bg, float* __restrict__ nf_out)
{
    extern __shared__ uint8_t smb[];
    const uint32_t sb = smem_u32(smb);
    uint32_t* s_xpu = (uint32_t*)(smb + XP_B);
    float* s_att   = (float*)(smb + ATT_B);
    float* s_alsp  = (float*)(smb + ALSP_B);
    float* s_aldp  = (float*)(smb + ALDP_B);
    float* s_alpha = (float*)(smb + ALPHA_B);

    const int tid  = threadIdx.x;
    const int wid  = tid >> 5;
    const int lane = tid & 31;
    const int hh   = wid >> 1;          // head 0..3
    const int ch2  = wid & 1;           // col half within head
    const long blk = blockIdx.x;

    for (int i = tid; i < 512; i += 256) {
        s_att[i]       = asrc[i];
        s_att[512 + i] = adst[i];
    }

    // A fill: 32 rows x 16 k-chunks = 512 tasks -> bf16 hi/lo swizzled
#pragma unroll
    for (int it = 0; it < 2; ++it) {
        int t = tid + 256 * it;
        int r = t >> 4, kb = t & 15;
        int il = r / 10, node = r - il * 10;
        long ig = blk * NI + il;
        uint32_t hi[4], lo[4];
        if (r < VROWS && ig < BT) {
            const float* src = nf_in + ig * NODE_F + node * HID + kb * 8;
            float4 a = *(const float4*)(src);
            float4 b = *(const float4*)(src + 4);
            split_bf16x2(a.x, a.y, hi[0], lo[0]);
            split_bf16x2(a.z, a.w, hi[1], lo[1]);
            split_bf16x2(b.x, b.y, hi[2], lo[2]);
            split_bf16x2(b.z, b.w, hi[3], lo[3]);
        } else {
#pragma unroll
            for (int j = 0; j < 4; ++j) { hi[j] = 0u; lo[j] = 0u; }
        }
        uint32_t off = (uint32_t)(r * 256 + ((kb ^ (r & 7)) * 16));
        *(uint4*)(smb + off)          = make_uint4(hi[0], hi[1], hi[2], hi[3]);
        *(uint4*)(smb + A_LO_B + off) = make_uint4(lo[0], lo[1], lo[2], lo[3]);
    }
    __syncthreads();

    const int q4 = lane >> 2;

    // Hoisted A-fragment addressing
    const int m_  = lane >> 3, i2_ = lane & 7;
    const int kbh = m_ >> 1;
    const int rbase = (m_ & 1) * 8 + i2_;
    uint32_t arow[2], rx7[2];
#pragma unroll
    for (int mt = 0; mt < 2; ++mt) {
        int r = mt * 16 + rbase;
        arow[mt] = sb + (uint32_t)(r * 256);
        rx7[mt]  = (uint32_t)(r & 7);
    }

    // ---- GEMM: two 32-col sub-passes, acc register-local per pass ----
    float pals[2][2], pald[2][2];
    pals[0][0]=pals[0][1]=pals[1][0]=pals[1][1]=0.f;
    pald[0][0]=pald[0][1]=pald[1][0]=pald[1][1]=0.f;
    uint32_t* xph = s_xpu + hh * XPH_U32;
    const float2* attS2 = (const float2*)(s_att + hh * 128);
    const float2* attD2 = (const float2*)(s_att + 512 + hh * 128);

#pragma unroll
    for (int s = 0; s < 2; ++s) {
        const uint4* Bw = (const uint4*)Wt + (hh * 4096 + (ch2 * 4 + s * 2) * 256 + lane);
        float acc[2][4][4];
#pragma unroll
        for (int mt = 0; mt < 2; ++mt)
#pragma unroll
            for (int n8 = 0; n8 < 4; ++n8)
#pragma unroll
                for (int j = 0; j < 4; ++j) acc[mt][n8][j] = 0.f;

#pragma unroll
        for (int kc = 0; kc < 8; ++kc) {
            const uint32_t kb = (uint32_t)(kc * 2 + kbh);
            uint32_t ahi[2][4], alo[2][4];
#pragma unroll
            for (int mt = 0; mt < 2; ++mt) {
                uint32_t addr = arow[mt] + ((kb ^ rx7[mt]) << 4);
                ldsm_x4(ahi[mt], addr);
                ldsm_x4(alo[mt], addr + A_LO_B);
            }
            uint4 b0 = Bw[kc * 32];
            uint4 b1 = Bw[kc * 32 + 256];
            uint4 l0 = Bw[kc * 32 + 2048];
            uint4 l1 = Bw[kc * 32 + 2304];
#pragma unroll
            for (int mt = 0; mt < 2; ++mt) {
                mma_bf16(acc[mt][0], ahi[mt], b0.x, b0.y);
                mma_bf16(acc[mt][1], ahi[mt], b0.z, b0.w);
                mma_bf16(acc[mt][2], ahi[mt], b1.x, b1.y);
                mma_bf16(acc[mt][3], ahi[mt], b1.z, b1.w);
                mma_bf16(acc[mt][0], alo[mt], b0.x, b0.y);
                mma_bf16(acc[mt][1], alo[mt], b0.z, b0.w);
                mma_bf16(acc[mt][2], alo[mt], b1.x, b1.y);
                mma_bf16(acc[mt][3], alo[mt], b1.z, b1.w);
                mma_bf16(acc[mt][0], ahi[mt], l0.x, l0.y);
                mma_bf16(acc[mt][1], ahi[mt], l0.z, l0.w);
                mma_bf16(acc[mt][2], ahi[mt], l1.x, l1.y);
                mma_bf16(acc[mt][3], ahi[mt], l1.z, l1.w);
            }
        }

        // xp store (half2, per-head plane) + logit partials (float2 att loads)
#pragma unroll
        for (int mt = 0; mt < 2; ++mt) {
            int r0 = mt * 16 + q4;
#pragma unroll
            for (int n8 = 0; n8 < 4; ++n8) {
                int cp = ch2 * 32 + s * 16 + n8 * 4 + (lane & 3);   // col pair index
                float2 av = attS2[cp];
                float2 dv = attD2[cp];
                pals[mt][0] = fmaf(acc[mt][n8][0], av.x, fmaf(acc[mt][n8][1], av.y, pals[mt][0]));
                pald[mt][0] = fmaf(acc[mt][n8][0], dv.x, fmaf(acc[mt][n8][1], dv.y, pald[mt][0]));
                pals[mt][1] = fmaf(acc[mt][n8][2], av.x, fmaf(acc[mt][n8][3], av.y, pals[mt][1]));
                pald[mt][1] = fmaf(acc[mt][n8][2], dv.x, fmaf(acc[mt][n8][3], dv.y, pald[mt][1]));
                __half2 v0 = __floats2half2_rn(acc[mt][n8][0], acc[mt][n8][1]);
                __half2 v1 = __floats2half2_rn(acc[mt][n8][2], acc[mt][n8][3]);
                xph[r0 * XPS_U32 + cp]       = *(uint32_t*)&v0;
                xph[(r0 + 8) * XPS_U32 + cp] = *(uint32_t*)&v1;
            }
        }
    }

#pragma unroll
    for (int mt = 0; mt < 2; ++mt)
#pragma unroll
        for (int j = 0; j < 2; ++j) {
            pals[mt][j] += __shfl_xor_sync(0xffffffffu, pals[mt][j], 1);
            pals[mt][j] += __shfl_xor_sync(0xffffffffu, pals[mt][j], 2);
            pald[mt][j] += __shfl_xor_sync(0xffffffffu, pald[mt][j], 1);
            pald[mt][j] += __shfl_xor_sync(0xffffffffu, pald[mt][j], 2);
        }
    if ((lane & 3) == 0) {
#pragma unroll
        for (int mt = 0; mt < 2; ++mt) {
            int r0 = mt * 16 + q4;
            s_alsp[wid * 32 + r0]     = pals[mt][0];
            s_alsp[wid * 32 + r0 + 8] = pals[mt][1];
            s_aldp[wid * 32 + r0]     = pald[mt][0];
            s_aldp[wid * 32 + r0 + 8] = pald[mt][1];
        }
    }
    __syncthreads();

    // ---- segment softmax (120 workers: 4 heads x 3 inst x 10 dst) ----
    if (tid < 120) {
        int th = tid / 30, rem = tid - th * 30;
        int il = rem / 10, dst = rem - il * 10, rb = il * 10;
        const float* asl = s_alsp + th * 64;
        const float* adl = s_aldp + th * 64;
        int rd = rb + dst;
        float ald = adl[rd] + adl[32 + rd];
        int s0 = c_start[dst], s1 = c_start[dst + 1];
        float vb[5], m = -1e30f;
        for (int k = s0; k < s1; ++k) {
            int rs = rb + c_src[k];
            float als = asl[rs] + asl[32 + rs];
            float v = als + ald;
            v = v > 0.f ? v : 0.2f * v;
            vb[k - s0] = v;
            m = fmaxf(m, v);
        }
        float ssum = 0.f;
        float eb[5];
        for (int k = s0; k < s1; ++k) {
            float ex = __expf(vb[k - s0] - m);
            ssum += ex;
            eb[k - s0] = ex;
        }
        float inv = 1.0f / ssum;
        for (int k = s0; k < s1; ++k)
            s_alpha[(il * NE + k) * 4 + th] = eb[k - s0] * inv;
    }
    __syncthreads();

    // ---- fused aggregation + mean + bias + GELU + residual ----
#pragma unroll
    for (int it = 0; it < 4; ++it) {
        int q = tid + 256 * it;                 // 960 float4 tasks
        if (q < 960) {
            int il = q / 320, rem = q - il * 320, dst = rem >> 5, f = (rem & 31) * 4;
            long ig = blk * NI + il;
            if (ig < BT) {
                int rb = il * 10;
                int s0 = c_start[dst], s1 = c_start[dst + 1];
                float4 a4; a4.x = a4.y = a4.z = a4.w = 0.f;
                const int u2base = f >> 2;       // uint2 index within row
                for (int k = s0; k < s1; ++k) {
                    int row = rb + c_src[k];
                    float4 al4 = *(const float4*)(s_alpha + (il * NE + k) * 4);
                    const uint32_t rowoff = row * XPS_U32;
                    float2 c0, c1;
                    {
                        uint2 p = ((const uint2*)(s_xpu + rowoff))[u2base];
                        c0 = __half22float2(*(__half2*)&p.x); c1 = __half22float2(*(__half2*)&p.y);
                        a4.x = fmaf(al4.x, c0.x, a4.x); a4.y = fmaf(al4.x, c0.y, a4.y);
                        a4.z = fmaf(al4.x, c1.x, a4.z); a4.w = fmaf(al4.x, c1.y, a4.w);
                    }
                    {
                        uint2 p = ((const uint2*)(s_xpu + XPH_U32 + rowoff))[u2base];
                        c0 = __half22float2(*(__half2*)&p.x); c1 = __half22float2(*(__half2*)&p.y);
                        a4.x = fmaf(al4.y, c0.x, a4.x); a4.y = fmaf(al4.y, c0.y, a4.y);
                        a4.z = fmaf(al4.y, c1.x, a4.z); a4.w = fmaf(al4.y, c1.y, a4.w);
                    }
                    {
                        uint2 p = ((const uint2*)(s_xpu + 2 * XPH_U32 + rowoff))[u2base];
                        c0 = __half22float2(*(__half2*)&p.x); c1 = __half22float2(*(__half2*)&p.y);
                        a4.x = fmaf(al4.z, c0.x, a4.x); a4.y = fmaf(al4.z, c0.y, a4.y);
                        a4.z = fmaf(al4.z, c1.x, a4.z); a4.w = fmaf(al4.z, c1.y, a4.w);
                    }
                    {
                        uint2 p = ((const uint2*)(s_xpu + 3 * XPH_U32 + rowoff))[u2base];
                        c0 = __half22float2(*(__half2*)&p.x); c1 = __half22float2(*(__half2*)&p.y);
                        a4.x = fmaf(al4.w, c0.x, a4.x); a4.y = fmaf(al4.w, c0.y, a4.y);
                        a4.z = fmaf(al4.w, c1.x, a4.z); a4.w = fmaf(al4.w, c1.y, a4.w);
                    }
                }
                float4 bgv = *(const float4*)(bg + f);
                float4 rs  = *(const float4*)(nf_in + ig * NODE_F + dst * HID + f);
                float4 w;
                w.x = gelu_exact(fmaf(0.25f, a4.x, bgv.x)) + rs.x;
                w.y = gelu_exact(fmaf(0.25f, a4.y, bgv.y)) + rs.y;
                w.z = gelu_exact(fmaf(0.25f, a4.z, bgv.z)) + rs.z;
                w.w = gelu_exact(fmaf(0.25f, a4.w, bgv.w)) + rs.w;
                *(float4*)(nf_out + ig * NODE_F + dst * HID + f) = w;
            }
        }
    }
}

// ---------------------------------------------------------------------------
extern "C" void kernel_launch(void* const* d_in, const int* in_sizes, int n_in,
                              void* d_out, int out_size)
{
    const float* x     = (const float*)d_in[0];
    const float* Wenc  = (const float*)d_in[1];
    const float* benc  = (const float*)d_in[2];
    const float* gamma = (const float*)d_in[3];
    const float* beta  = (const float*)d_in[4];
    const float* Wg    = (const float*)d_in[5];
    const float* asrc  = (const float*)d_in[6];
    const float* adst  = (const float*)d_in[7];
    const float* bg    = (const float*)d_in[8];

    float* out = (float*)d_out;
    float* region_out = (out_size >= 2 * NTOT) ? out + NTOT : nullptr;

    float* nf0;  cudaGetSymbolAddress((void**)&nf0, g_nf0);
    float* nf1;  cudaGetSymbolAddress((void**)&nf1, g_nf1);
    uint8_t* wt; cudaGetSymbolAddress((void**)&wt, g_Wt);

    cudaFuncSetAttribute(gat_mma_kernel, cudaFuncAttributeMaxDynamicSharedMemorySize, SM_DYNBYTES);

    wt_enc_kernel<<<12 + BT / 2, 256>>>(Wg, x, Wenc, benc, gamma, beta, nf0, region_out);

    gat_mma_kernel<<<GRID_GAT, 256, SM_DYNBYTES>>>(nf0, wt,               asrc,        adst,        bg,       nf1);
    gat_mma_kernel<<<GRID_GAT, 256, SM_DYNBYTES>>>(nf1, wt + 4 * 65536,   asrc + 512,  adst + 512,  bg + 128, nf0);
    gat_mma_kernel<<<GRID_GAT, 256, SM_DYNBYTES>>>(nf0, wt + 8 * 65536,   asrc + 1024, adst + 1024, bg + 256, out);
}